// round 1
// baseline (speedup 1.0000x reference)
#include <cuda_runtime.h>
#include <cstdint>
#include <cstddef>

#define NN   50000
#define NE   600000
#define C    128
#define NG   128
#define OUTC 10

// ---------------- scratch (static device globals: allocation-free) ----------
__device__ float g_h0[NN * C];
__device__ float g_h1[NN * C];
__device__ float g_agg[NN * C];
__device__ float g_inv[NN];      // 1/max(deg,1)
__device__ float g_ginv[NG];     // 1/max(graph_cnt,1)
__device__ float g_pool[NG * C];
__device__ float g_WT[6][C * C]; // transposed weights: [k][j]
__device__ int   g_cnt[NN];      // in-degree
__device__ int   g_gcnt[NG];     // nodes per graph
__device__ int   g_off[NN + 1];  // CSR offsets (by dst)
__device__ int   g_cur[NN];      // fill cursors
__device__ int   g_adj[NE];      // CSR: src list grouped by dst
__device__ int   g_src[NE];
__device__ int   g_dst[NE];
__device__ int   g_batch[NN];
__device__ int   g_is64;

// ---------------- index dtype detection + conversion ------------------------
// If edge_index arrived as int64 (little-endian, values < 2^31), every odd
// 32-bit word is zero. For int32, odd words are random src ids in [0,50000).
__global__ void detect_kernel(const unsigned int* __restrict__ ei_words) {
    int is64 = 1;
#pragma unroll
    for (int i = 0; i < 16; i++) {
        if (ei_words[1 + 74 * i] != 0u) { is64 = 0; break; }
    }
    g_is64 = is64;
}

__global__ void convert_idx(const void* __restrict__ ei, const void* __restrict__ batch) {
    int i = blockIdx.x * blockDim.x + threadIdx.x;
    const bool is64 = (g_is64 != 0);
    if (i < NE) {
        if (is64) {
            const long long* p = (const long long*)ei;
            g_src[i] = (int)p[i];
            g_dst[i] = (int)p[NE + i];
        } else {
            const int* p = (const int*)ei;
            g_src[i] = p[i];
            g_dst[i] = p[NE + i];
        }
    }
    if (i < NN) {
        if (is64) g_batch[i] = (int)((const long long*)batch)[i];
        else      g_batch[i] = ((const int*)batch)[i];
    }
}

// ---------------- setup: zero + degree + CSR build --------------------------
__global__ void zero_setup() {
    int i = blockIdx.x * blockDim.x + threadIdx.x;
    if (i < NN) g_cnt[i] = 0;
    if (i < NG) g_gcnt[i] = 0;
    if (i < NG * C) g_pool[i] = 0.0f;
}

__global__ void degree_kernel() {
    int e = blockIdx.x * blockDim.x + threadIdx.x;
    if (e < NE) atomicAdd(&g_cnt[g_dst[e]], 1);
}

__global__ void batchcnt_kernel() {
    int i = blockIdx.x * blockDim.x + threadIdx.x;
    if (i < NN) atomicAdd(&g_gcnt[g_batch[i]], 1);
}

// single-block exclusive scan over degrees -> offsets (+ cursor copy)
__global__ void scan_kernel() {
    __shared__ int part[1024];
    const int t = threadIdx.x;
    const int CH = (NN + 1023) / 1024;  // 49
    const int base = t * CH;
    int s = 0;
    for (int i = 0; i < CH; i++) {
        int idx = base + i;
        if (idx < NN) s += g_cnt[idx];
    }
    part[t] = s;
    __syncthreads();
    for (int d = 1; d < 1024; d <<= 1) {
        int v = part[t];
        int add = (t >= d) ? part[t - d] : 0;
        __syncthreads();
        part[t] = v + add;
        __syncthreads();
    }
    int run = (t == 0) ? 0 : part[t - 1];
    for (int i = 0; i < CH; i++) {
        int idx = base + i;
        if (idx < NN) {
            g_off[idx] = run;
            g_cur[idx] = run;
            run += g_cnt[idx];
        }
    }
    if (t == 0) g_off[NN] = NE;
}

__global__ void inv_kernel() {
    int i = blockIdx.x * blockDim.x + threadIdx.x;
    if (i < NN) g_inv[i] = 1.0f / fmaxf((float)g_cnt[i], 1.0f);
    if (i < NG) g_ginv[i] = 1.0f / fmaxf((float)g_gcnt[i], 1.0f);
}

__global__ void fill_kernel() {
    int e = blockIdx.x * blockDim.x + threadIdx.x;
    if (e < NE) {
        int dst = g_dst[e];
        int pos = atomicAdd(&g_cur[dst], 1);
        g_adj[pos] = g_src[e];
    }
}

// ---------------- weight transpose: W[j][k] -> WT[k][j] ---------------------
__global__ void transpose_w(const float* __restrict__ W, int slot) {
    int i = blockIdx.x * blockDim.x + threadIdx.x;  // 16384
    int j = i >> 7;
    int k = i & 127;
    g_WT[slot][k * C + j] = W[i];
}

// ---------------- mean aggregation (atomic-free gather) ---------------------
// warp per dst node; lane owns 4 channels; writes agg already divided by deg.
__global__ void gather_kernel(int in_sel, const float* __restrict__ x) {
    const float* hin = (in_sel == 0) ? x : ((in_sel == 1) ? g_h0 : g_h1);
    int gid = blockIdx.x * blockDim.x + threadIdx.x;
    int node = gid >> 5;
    int lane = gid & 31;
    if (node >= NN) return;
    int beg = g_off[node];
    int end = g_off[node + 1];
    float4 acc = make_float4(0.f, 0.f, 0.f, 0.f);
    for (int i = beg; i < end; i++) {
        int src = g_adj[i];
        const float4 v = *(const float4*)(hin + (size_t)src * C + lane * 4);
        acc.x += v.x; acc.y += v.y; acc.z += v.z; acc.w += v.w;
    }
    const float s = g_inv[node];
    acc.x *= s; acc.y *= s; acc.z *= s; acc.w *= s;
    *(float4*)(g_agg + (size_t)node * C + lane * 4) = acc;
}

// ---------------- fused SAGE layer GEMM -------------------------------------
// hout = relu(agg @ WlT + hin @ WrT + bl), all [*,128], fp32.
// BM=64, BN=128, BK=16, 256 threads, 8x4 register tile per thread.
__global__ void __launch_bounds__(256) sage_gemm(
    int in_sel, const float* __restrict__ x,
    int wslot, const float* __restrict__ bl, int out_sel)
{
    const float* hin = (in_sel == 0) ? x : ((in_sel == 1) ? g_h0 : g_h1);
    float* hout = out_sel ? g_h1 : g_h0;

    __shared__ float As[16][64];    // [k][row]
    __shared__ float Ws[16][128];   // [k][col]

    const int tid = threadIdx.x;
    const int tx = tid & 31;        // col group: cols tx*4..tx*4+3
    const int ty = tid >> 5;        // row group: rows ty*8..ty*8+7
    const int bm = blockIdx.x * 64;

    const int lr = tid >> 2;        // 0..63  A-load row
    const int lg = tid & 3;         // 0..3   A-load col group (16B)
    const int arow = bm + lr;
    const bool arow_ok = (arow < NN);

    float acc[8][4];
#pragma unroll
    for (int m = 0; m < 8; m++)
#pragma unroll
        for (int c = 0; c < 4; c++) acc[m][c] = 0.0f;

#pragma unroll
    for (int phase = 0; phase < 2; phase++) {
        const float* A = phase ? hin : g_agg;        // agg is pre-scaled
        const float* WT = g_WT[wslot + phase];       // wslot: WlT, wslot+1: WrT
#pragma unroll
        for (int kk = 0; kk < C; kk += 16) {
            float4 a4 = make_float4(0.f, 0.f, 0.f, 0.f);
            if (arow_ok)
                a4 = *(const float4*)(A + (size_t)arow * C + kk + lg * 4);
            As[lg * 4 + 0][lr] = a4.x;
            As[lg * 4 + 1][lr] = a4.y;
            As[lg * 4 + 2][lr] = a4.z;
            As[lg * 4 + 3][lr] = a4.w;
#pragma unroll
            for (int r = 0; r < 2; r++) {
                int v = tid + r * 256;
                int k = v >> 5;
                int jg = v & 31;
                *(float4*)&Ws[k][jg * 4] =
                    *(const float4*)(WT + (size_t)(kk + k) * C + jg * 4);
            }
            __syncthreads();
#pragma unroll
            for (int k = 0; k < 16; k++) {
                const float4 b4 = *(const float4*)&Ws[k][tx * 4];
                const float4 a0 = *(const float4*)&As[k][ty * 8];
                const float4 a1 = *(const float4*)&As[k][ty * 8 + 4];
                const float a[8] = {a0.x, a0.y, a0.z, a0.w, a1.x, a1.y, a1.z, a1.w};
#pragma unroll
                for (int m = 0; m < 8; m++) {
                    acc[m][0] += a[m] * b4.x;
                    acc[m][1] += a[m] * b4.y;
                    acc[m][2] += a[m] * b4.z;
                    acc[m][3] += a[m] * b4.w;
                }
            }
            __syncthreads();
        }
    }

    const float4 bb = *(const float4*)(bl + tx * 4);
#pragma unroll
    for (int m = 0; m < 8; m++) {
        int grow = bm + ty * 8 + m;
        if (grow < NN) {
            float4 o;
            o.x = fmaxf(acc[m][0] + bb.x, 0.0f);
            o.y = fmaxf(acc[m][1] + bb.y, 0.0f);
            o.z = fmaxf(acc[m][2] + bb.z, 0.0f);
            o.w = fmaxf(acc[m][3] + bb.w, 0.0f);
            *(float4*)(hout + (size_t)grow * C + tx * 4) = o;
        }
    }
}

// ---------------- global mean pool (reads g_h0 = layer-2 output) ------------
__global__ void pool_kernel() {
    int gid = blockIdx.x * blockDim.x + threadIdx.x;
    int node = gid >> 5;
    int lane = gid & 31;
    if (node >= NN) return;
    int g = g_batch[node];
    const float4 v = *(const float4*)(g_h0 + (size_t)node * C + lane * 4);
    float* p = g_pool + g * C + lane * 4;
    atomicAdd(p + 0, v.x);
    atomicAdd(p + 1, v.y);
    atomicAdd(p + 2, v.z);
    atomicAdd(p + 3, v.w);
}

// ---------------- head: out[g][o] = mean_pool[g] . W_lin[o] + b_lin ---------
__global__ void out_kernel(const float* __restrict__ W_lin,
                           const float* __restrict__ b_lin,
                           float* __restrict__ out) {
    int g = blockIdx.x;
    int c = threadIdx.x;  // 128 threads
    __shared__ float sv[C];
    sv[c] = g_pool[g * C + c] * g_ginv[g];
    __syncthreads();
    if (c < OUTC) {
        float s = b_lin[c];
#pragma unroll
        for (int k = 0; k < C; k++) s += sv[k] * W_lin[c * C + k];
        out[g * OUTC + c] = s;
    }
}

// ---------------- launch ----------------------------------------------------
extern "C" void kernel_launch(void* const* d_in, const int* in_sizes, int n_in,
                              void* d_out, int out_size) {
    const float* x      = (const float*)d_in[0];
    const void*  ei     = d_in[1];
    const void*  batch  = d_in[2];
    const float* Wl[3]  = {(const float*)d_in[3], (const float*)d_in[6], (const float*)d_in[9]};
    const float* blv[3] = {(const float*)d_in[4], (const float*)d_in[7], (const float*)d_in[10]};
    const float* Wr[3]  = {(const float*)d_in[5], (const float*)d_in[8], (const float*)d_in[11]};
    const float* W_lin  = (const float*)d_in[12];
    const float* b_lin  = (const float*)d_in[13];
    float* out = (float*)d_out;

    const int TB = 256;
    const int gE = (NE + TB - 1) / TB;       // 2344
    const int gN = (NN + TB - 1) / TB;       // 196
    const int gW = (NN * 32 + TB - 1) / TB;  // 6250 (warp per node)
    const int gG = (NN / 64 + 1);            // 782 row tiles of 64

    detect_kernel<<<1, 1>>>((const unsigned int*)ei);
    convert_idx<<<gE, TB>>>(ei, batch);
    zero_setup<<<gN, TB>>>();
    degree_kernel<<<gE, TB>>>();
    batchcnt_kernel<<<gN, TB>>>();
    scan_kernel<<<1, 1024>>>();
    inv_kernel<<<gN, TB>>>();
    fill_kernel<<<gE, TB>>>();

    for (int l = 0; l < 3; l++) {
        transpose_w<<<64, TB>>>(Wl[l], 2 * l);
        transpose_w<<<64, TB>>>(Wr[l], 2 * l + 1);
    }

    // layer 0: x -> h0 ; layer 1: h0 -> h1 ; layer 2: h1 -> h0
    const int in_sel[3]  = {0, 1, 2};
    const int out_sel[3] = {0, 1, 0};
    for (int l = 0; l < 3; l++) {
        gather_kernel<<<gW, TB>>>(in_sel[l], x);
        sage_gemm<<<gG, TB>>>(in_sel[l], x, 2 * l, blv[l], out_sel[l]);
    }

    pool_kernel<<<gW, TB>>>();
    out_kernel<<<NG, C>>>(W_lin, b_lin, out);
}

// round 3
// speedup vs baseline: 1.2239x; 1.2239x over previous
#include <cuda_runtime.h>
#include <cuda_bf16.h>
#include <cstdint>
#include <cstddef>

#define NN   50000
#define NE   600000
#define C    128
#define NG   128
#define OUTC 10
#define NT   391          // ceil(NN/128) M-tiles

// ---------------- scratch (static device globals: allocation-free) ----------
__device__ float g_h0[NN * C];
__device__ float g_h1[NN * C];
__device__ float g_inv[NN];
__device__ float g_ginv[NG];
__device__ float g_pool[NG * C];
// split feature buffers: per row 128 u32 words: [0..63]=hi bf16 pairs, [64..127]=lo pairs
__device__ uint4 g_aggs4[NN * 32];
__device__ uint4 g_hsA4[NN * 32];
__device__ uint4 g_hsB4[NN * 32];
// weights, split: [layer][src(2)][n(128)][128 u32 words], as uint4
__device__ uint4 g_Bp4[3][8192];
__device__ int   g_cnt[NN];
__device__ int   g_gcnt[NG];
__device__ int   g_off[NN + 1];
__device__ int   g_cur[NN];
__device__ int   g_adj[NE];
__device__ int   g_src[NE];
__device__ int   g_dst[NE];
__device__ int   g_batch[NN];
__device__ int   g_is64;

// ---------------- split helpers ---------------------------------------------
// hi = top-16-bits (exactly bf16), lo = rn-bf16 of residual. Pack 2 channels/u32,
// low half = even channel.
__device__ __forceinline__ void split2(float a, float b, uint32_t& hi, uint32_t& lo) {
    uint32_t ua = __float_as_uint(a);
    uint32_t ub = __float_as_uint(b);
    hi = __byte_perm(ua, ub, 0x7632);
    float ra = a - __uint_as_float(ua & 0xFFFF0000u);
    float rb = b - __uint_as_float(ub & 0xFFFF0000u);
    asm("cvt.rn.bf16x2.f32 %0, %1, %2;" : "=r"(lo) : "f"(rb), "f"(ra));
}

// ---------------- mma.sync bf16 m16n8k16 ------------------------------------
__device__ __forceinline__ void mma_bf16(float& d0, float& d1, float& d2, float& d3,
                                         uint32_t a0, uint32_t a1, uint32_t a2, uint32_t a3,
                                         uint32_t b0, uint32_t b1) {
    asm volatile(
        "mma.sync.aligned.m16n8k16.row.col.f32.bf16.bf16.f32 "
        "{%0,%1,%2,%3}, {%4,%5,%6,%7}, {%8,%9}, {%0,%1,%2,%3};"
        : "+f"(d0), "+f"(d1), "+f"(d2), "+f"(d3)
        : "r"(a0), "r"(a1), "r"(a2), "r"(a3), "r"(b0), "r"(b1));
}

// ---------------- index dtype detection + conversion ------------------------
__global__ void detect_kernel(const unsigned int* __restrict__ ei_words) {
    int is64 = 1;
#pragma unroll
    for (int i = 0; i < 16; i++)
        if (ei_words[1 + 74 * i] != 0u) { is64 = 0; break; }
    g_is64 = is64;
}

__global__ void convert_idx(const void* __restrict__ ei, const void* __restrict__ batch) {
    int i = blockIdx.x * blockDim.x + threadIdx.x;
    const bool is64 = (g_is64 != 0);
    if (i < NE) {
        if (is64) {
            const long long* p = (const long long*)ei;
            g_src[i] = (int)p[i];
            g_dst[i] = (int)p[NE + i];
        } else {
            const int* p = (const int*)ei;
            g_src[i] = p[i];
            g_dst[i] = p[NE + i];
        }
    }
    if (i < NN) {
        if (is64) g_batch[i] = (int)((const long long*)batch)[i];
        else      g_batch[i] = ((const int*)batch)[i];
    }
}

// ---------------- setup: zero + degree + CSR build --------------------------
__global__ void zero_setup() {
    int i = blockIdx.x * blockDim.x + threadIdx.x;
    if (i < NN) g_cnt[i] = 0;
    if (i < NG) g_gcnt[i] = 0;
    if (i < NG * C) g_pool[i] = 0.0f;
}
__global__ void degree_kernel() {
    int e = blockIdx.x * blockDim.x + threadIdx.x;
    if (e < NE) atomicAdd(&g_cnt[g_dst[e]], 1);
}
__global__ void batchcnt_kernel() {
    int i = blockIdx.x * blockDim.x + threadIdx.x;
    if (i < NN) atomicAdd(&g_gcnt[g_batch[i]], 1);
}
__global__ void scan_kernel() {
    __shared__ int part[1024];
    const int t = threadIdx.x;
    const int CH = (NN + 1023) / 1024;
    const int base = t * CH;
    int s = 0;
    for (int i = 0; i < CH; i++) {
        int idx = base + i;
        if (idx < NN) s += g_cnt[idx];
    }
    part[t] = s;
    __syncthreads();
    for (int d = 1; d < 1024; d <<= 1) {
        int v = part[t];
        int add = (t >= d) ? part[t - d] : 0;
        __syncthreads();
        part[t] = v + add;
        __syncthreads();
    }
    int run = (t == 0) ? 0 : part[t - 1];
    for (int i = 0; i < CH; i++) {
        int idx = base + i;
        if (idx < NN) { g_off[idx] = run; g_cur[idx] = run; run += g_cnt[idx]; }
    }
    if (t == 0) g_off[NN] = NE;
}
__global__ void inv_kernel() {
    int i = blockIdx.x * blockDim.x + threadIdx.x;
    if (i < NN) g_inv[i] = 1.0f / fmaxf((float)g_cnt[i], 1.0f);
    if (i < NG) g_ginv[i] = 1.0f / fmaxf((float)g_gcnt[i], 1.0f);
}
__global__ void fill_kernel() {
    int e = blockIdx.x * blockDim.x + threadIdx.x;
    if (e < NE) {
        int dst = g_dst[e];
        int pos = atomicAdd(&g_cur[dst], 1);
        g_adj[pos] = g_src[e];
    }
}

// ---------------- weight prep: split W into hi/lo words ---------------------
// thread per word-pair: g_Bp[l][(s*128+n)*128 + w] = hi(ch 2w,2w+1); +64 = lo
__global__ void prep_bp(const float* __restrict__ Wl, const float* __restrict__ Wr, int layer) {
    int idx = blockIdx.x * blockDim.x + threadIdx.x;   // 2*128*64 = 16384
    if (idx >= 16384) return;
    int s = idx >> 13;
    int n = (idx >> 6) & 127;
    int w = idx & 63;
    const float* W = s ? Wr : Wl;
    float a = W[n * 128 + 2 * w];
    float b = W[n * 128 + 2 * w + 1];
    uint32_t hi, lo;
    split2(a, b, hi, lo);
    uint32_t* Bp = (uint32_t*)g_Bp4[layer];
    Bp[(s * 128 + n) * 128 + w] = hi;
    Bp[(s * 128 + n) * 128 + 64 + w] = lo;
}

// ---------------- split x into g_hsA ----------------------------------------
__global__ void split_x(const float* __restrict__ x) {
    int id = blockIdx.x * blockDim.x + threadIdx.x;  // NN*32
    if (id >= NN * 32) return;
    int node = id >> 5;
    int f4 = id & 31;
    const float4 v = *(const float4*)(x + (size_t)node * C + f4 * 4);
    uint32_t h0, l0, h1, l1;
    split2(v.x, v.y, h0, l0);
    split2(v.z, v.w, h1, l1);
    uint32_t* out = (uint32_t*)g_hsA4;
    *(uint2*)(out + (size_t)node * 128 + f4 * 2) = make_uint2(h0, h1);
    *(uint2*)(out + (size_t)node * 128 + 64 + f4 * 2) = make_uint2(l0, l1);
}

// ---------------- mean aggregation + fused split ----------------------------
// warp per dst node; lane owns 4 channels; writes split(mean) into g_aggs.
__global__ void gather_kernel(int in_sel, const float* __restrict__ x) {
    const float* hin = (in_sel == 0) ? x : ((in_sel == 1) ? g_h0 : g_h1);
    int gid = blockIdx.x * blockDim.x + threadIdx.x;
    int node = gid >> 5;
    int lane = gid & 31;
    if (node >= NN) return;
    int beg = g_off[node];
    int end = g_off[node + 1];
    float4 acc = make_float4(0.f, 0.f, 0.f, 0.f);
    for (int i = beg; i < end; i++) {
        int src = g_adj[i];
        const float4 v = *(const float4*)(hin + (size_t)src * C + lane * 4);
        acc.x += v.x; acc.y += v.y; acc.z += v.z; acc.w += v.w;
    }
    const float s = g_inv[node];
    acc.x *= s; acc.y *= s; acc.z *= s; acc.w *= s;
    uint32_t h0, l0, h1, l1;
    split2(acc.x, acc.y, h0, l0);
    split2(acc.z, acc.w, h1, l1);
    uint32_t* out = (uint32_t*)g_aggs4;
    *(uint2*)(out + (size_t)node * 128 + lane * 2) = make_uint2(h0, h1);
    *(uint2*)(out + (size_t)node * 128 + 64 + lane * 2) = make_uint2(l0, l1);
}

// ---------------- tensor-core SAGE layer (mma.sync bf16) --------------------
// hout = relu([agg|hin] @ [Wl|Wr]^T + bl) via 3-pairing hi/lo split GEMM.
// SMEM rows padded to 132 u32 words (conflict-free lds).
#define RSW 132
#define A_WORDS (128 * RSW)
#define SMEM_WORDS (3 * A_WORDS)   // A, B0, B1

__global__ void __launch_bounds__(256, 1) sage_gemm_mma(
    int layer, int hs_in_sel, int out_sel, int do_split,
    const float* __restrict__ bl)
{
    extern __shared__ uint32_t smem[];
    uint32_t* As  = smem;
    uint32_t* B0s = smem + A_WORDS;
    uint32_t* B1s = smem + 2 * A_WORDS;

    const uint32_t* Ain0 = (const uint32_t*)g_aggs4;
    const uint32_t* Ain1 = hs_in_sel ? (const uint32_t*)g_hsB4 : (const uint32_t*)g_hsA4;
    uint32_t* hs_out = hs_in_sel ? (uint32_t*)g_hsA4 : (uint32_t*)g_hsB4;
    float* hout = out_sel ? g_h1 : g_h0;

    const int tid = threadIdx.x;
    const int wid = tid >> 5;
    const int lane = tid & 31;
    const int gid = lane >> 2;
    const int tig = lane & 3;

    // Load all B (2 sources x 128 n x 128 words) into SMEM, padded rows.
    {
        const uint4* Bp = g_Bp4[layer];
#pragma unroll
        for (int i = 0; i < 32; i++) {
            int id = tid + 256 * i;          // 8192 uint4
            int s = id >> 12;
            int n = (id >> 5) & 127;
            int q = id & 31;
            uint4 v = Bp[id];
            uint32_t* dst = (s ? B1s : B0s) + n * RSW + q * 4;
            *(uint4*)dst = v;
        }
    }

    for (int tile = blockIdx.x; tile < NT; tile += gridDim.x) {
        const int mbase = tile * 128;
        float acc[16][4];
#pragma unroll
        for (int nf = 0; nf < 16; nf++)
#pragma unroll
            for (int i = 0; i < 4; i++) acc[nf][i] = 0.0f;

        for (int s = 0; s < 2; s++) {
            const uint32_t* Ag = s ? Ain1 : Ain0;
            const uint32_t* Bs = s ? B1s : B0s;
            __syncthreads();
            // fill A tile: 128 rows x 128 words
#pragma unroll
            for (int i = 0; i < 16; i++) {
                int id = tid + 256 * i;
                int r = id >> 5;
                int q = id & 31;
                int grow = mbase + r;
                if (grow >= NN) grow = 0;
                uint4 v = *(const uint4*)(Ag + (size_t)grow * 128 + q * 4);
                *(uint4*)(As + r * RSW + q * 4) = v;
            }
            __syncthreads();

            const uint32_t* Aw = As + (wid * 16 + gid) * RSW + tig;
            const uint32_t* Bw = Bs + gid * RSW + tig;
            for (int ks = 0; ks < 8; ks++) {
                const uint32_t* Ap = Aw + ks * 8;
                uint32_t ah0 = Ap[0],        ah2 = Ap[4];
                uint32_t ah1 = Ap[8 * RSW],  ah3 = Ap[8 * RSW + 4];
                uint32_t al0 = Ap[64],       al2 = Ap[68];
                uint32_t al1 = Ap[8 * RSW + 64], al3 = Ap[8 * RSW + 68];
                const uint32_t* Bq = Bw + ks * 8;
#pragma unroll
                for (int nf = 0; nf < 16; nf++) {
                    const uint32_t* Bn = Bq + nf * (8 * RSW);
                    uint32_t bh0 = Bn[0], bh1 = Bn[4];
                    mma_bf16(acc[nf][0], acc[nf][1], acc[nf][2], acc[nf][3],
                             ah0, ah1, ah2, ah3, bh0, bh1);
                    mma_bf16(acc[nf][0], acc[nf][1], acc[nf][2], acc[nf][3],
                             al0, al1, al2, al3, bh0, bh1);
                    uint32_t bl0 = Bn[64], bl1 = Bn[68];
                    mma_bf16(acc[nf][0], acc[nf][1], acc[nf][2], acc[nf][3],
                             ah0, ah1, ah2, ah3, bl0, bl1);
                }
            }
        }

        // epilogue: bias + relu + fp32 store + optional split store
        const int r0 = mbase + wid * 16 + gid;
        const int r1 = r0 + 8;
#pragma unroll
        for (int nf = 0; nf < 16; nf++) {
            const int col = nf * 8 + tig * 2;
            const float2 bb = *(const float2*)(bl + col);
            float v00 = fmaxf(acc[nf][0] + bb.x, 0.0f);
            float v01 = fmaxf(acc[nf][1] + bb.y, 0.0f);
            float v10 = fmaxf(acc[nf][2] + bb.x, 0.0f);
            float v11 = fmaxf(acc[nf][3] + bb.y, 0.0f);
            if (r0 < NN) *(float2*)(hout + (size_t)r0 * C + col) = make_float2(v00, v01);
            if (r1 < NN) *(float2*)(hout + (size_t)r1 * C + col) = make_float2(v10, v11);
            if (do_split) {
                const int w = nf * 4 + tig;
                uint32_t hi, lo;
                if (r0 < NN) {
                    split2(v00, v01, hi, lo);
                    hs_out[(size_t)r0 * 128 + w] = hi;
                    hs_out[(size_t)r0 * 128 + 64 + w] = lo;
                }
                if (r1 < NN) {
                    split2(v10, v11, hi, lo);
                    hs_out[(size_t)r1 * 128 + w] = hi;
                    hs_out[(size_t)r1 * 128 + 64 + w] = lo;
                }
            }
        }
    }
}

// ---------------- global mean pool (reads g_h0 = layer-2 output) ------------
__global__ void pool_kernel() {
    int gid = blockIdx.x * blockDim.x + threadIdx.x;
    int node = gid >> 5;
    int lane = gid & 31;
    if (node >= NN) return;
    int g = g_batch[node];
    const float4 v = *(const float4*)(g_h0 + (size_t)node * C + lane * 4);
    float* p = g_pool + g * C + lane * 4;
    atomicAdd(p + 0, v.x);
    atomicAdd(p + 1, v.y);
    atomicAdd(p + 2, v.z);
    atomicAdd(p + 3, v.w);
}

// ---------------- head ------------------------------------------------------
__global__ void out_kernel(const float* __restrict__ W_lin,
                           const float* __restrict__ b_lin,
                           float* __restrict__ out) {
    int g = blockIdx.x;
    int c = threadIdx.x;
    __shared__ float sv[C];
    sv[c] = g_pool[g * C + c] * g_ginv[g];
    __syncthreads();
    if (c < OUTC) {
        float s = b_lin[c];
#pragma unroll
        for (int k = 0; k < C; k++) s += sv[k] * W_lin[c * C + k];
        out[g * OUTC + c] = s;
    }
}

// ---------------- launch ----------------------------------------------------
extern "C" void kernel_launch(void* const* d_in, const int* in_sizes, int n_in,
                              void* d_out, int out_size) {
    const float* x      = (const float*)d_in[0];
    const void*  ei     = d_in[1];
    const void*  batch  = d_in[2];
    const float* Wl[3]  = {(const float*)d_in[3], (const float*)d_in[6], (const float*)d_in[9]};
    const float* blv[3] = {(const float*)d_in[4], (const float*)d_in[7], (const float*)d_in[10]};
    const float* Wr[3]  = {(const float*)d_in[5], (const float*)d_in[8], (const float*)d_in[11]};
    const float* W_lin  = (const float*)d_in[12];
    const float* b_lin  = (const float*)d_in[13];
    float* out = (float*)d_out;

    static int smem_set = 0;
    if (!smem_set) {
        cudaFuncSetAttribute(sage_gemm_mma,
                             cudaFuncAttributeMaxDynamicSharedMemorySize,
                             SMEM_WORDS * 4);
        smem_set = 1;
    }

    const int TB = 256;
    const int gE = (NE + TB - 1) / TB;
    const int gN = (NN + TB - 1) / TB;
    const int gW = (NN * 32 + TB - 1) / TB;

    detect_kernel<<<1, 1>>>((const unsigned int*)ei);
    convert_idx<<<gE, TB>>>(ei, batch);
    zero_setup<<<gN, TB>>>();
    degree_kernel<<<gE, TB>>>();
    batchcnt_kernel<<<gN, TB>>>();
    scan_kernel<<<1, 1024>>>();
    inv_kernel<<<gN, TB>>>();
    fill_kernel<<<gE, TB>>>();

    for (int l = 0; l < 3; l++)
        prep_bp<<<64, TB>>>(Wl[l], Wr[l], l);
    split_x<<<gW, TB>>>(x);

    // layer l: gather(h_{l-1}) -> aggs; gemm: [aggs | hs_in] -> h fp32 + hs_out
    // l0: gather(x),  hs_in=A(x),  fp32 out h0, split out -> B
    // l1: gather(h0), hs_in=B,     fp32 out h1, split out -> A
    // l2: gather(h1), hs_in=A,     fp32 out h0, no split
    const int in_sel[3]  = {0, 1, 2};
    const int hs_sel[3]  = {0, 1, 0};   // 0 = read A, 1 = read B
    const int out_sel[3] = {0, 1, 0};
    const int do_spl[3]  = {1, 1, 0};
    for (int l = 0; l < 3; l++) {
        gather_kernel<<<gW, TB>>>(in_sel[l], x);
        sage_gemm_mma<<<148, TB, SMEM_WORDS * 4>>>(l, hs_sel[l], out_sel[l], do_spl[l], blv[l]);
    }

    pool_kernel<<<gW, TB>>>();
    out_kernel<<<NG, C>>>(W_lin, b_lin, out);
}

// round 5
// speedup vs baseline: 1.8230x; 1.4895x over previous
#include <cuda_runtime.h>
#include <cuda_bf16.h>
#include <cstdint>
#include <cstddef>

#define NN   50000
#define NE   600000
#define C    128
#define NG   128
#define OUTC 10
#define NT   391          // ceil(NN/128) M-tiles

// ---------------- scratch (static device globals: allocation-free) ----------
__device__ float g_h0[NN * C];
__device__ float g_h1[NN * C];
__device__ float g_inv[NN];
__device__ float g_ginv[NG];
__device__ float g_pool[NG * C];
// split feature buffers: per row 128 u32 words: [0..63]=hi bf16 pairs, [64..127]=lo pairs
__device__ uint4 g_aggs4[NN * 32];
__device__ uint4 g_hsA4[NN * 32];
__device__ uint4 g_hsB4[NN * 32];
// weights, split: [layer][src(2)][n(128)][128 u32 words], as uint4
__device__ uint4 g_Bp4[3][8192];
__device__ int   g_cnt[NN];
__device__ int   g_gcnt[NG];
__device__ int   g_off[NN + 1];
__device__ int   g_cur[NN];
__device__ int   g_adj[NE];
__device__ int   g_src[NE];
__device__ int   g_dst[NE];
__device__ int   g_batch[NN];
__device__ int   g_part[256];    // per-block degree sums (196 used)
__device__ int   g_pbase[256];   // exclusive base per block
__device__ int   g_is64;

// ---------------- split helpers ---------------------------------------------
__device__ __forceinline__ void split2(float a, float b, uint32_t& hi, uint32_t& lo) {
    uint32_t ua = __float_as_uint(a);
    uint32_t ub = __float_as_uint(b);
    hi = __byte_perm(ua, ub, 0x7632);
    float ra = a - __uint_as_float(ua & 0xFFFF0000u);
    float rb = b - __uint_as_float(ub & 0xFFFF0000u);
    asm("cvt.rn.bf16x2.f32 %0, %1, %2;" : "=r"(lo) : "f"(rb), "f"(ra));
}

// ---------------- mma.sync bf16 m16n8k16 ------------------------------------
__device__ __forceinline__ void mma_bf16(float* d,
                                         uint32_t a0, uint32_t a1, uint32_t a2, uint32_t a3,
                                         uint32_t b0, uint32_t b1) {
    asm volatile(
        "mma.sync.aligned.m16n8k16.row.col.f32.bf16.bf16.f32 "
        "{%0,%1,%2,%3}, {%4,%5,%6,%7}, {%8,%9}, {%0,%1,%2,%3};"
        : "+f"(d[0]), "+f"(d[1]), "+f"(d[2]), "+f"(d[3])
        : "r"(a0), "r"(a1), "r"(a2), "r"(a3), "r"(b0), "r"(b1));
}

// ---------------- index dtype detection -------------------------------------
__global__ void detect_kernel(const unsigned int* __restrict__ ei_words) {
    int is64 = 1;
#pragma unroll
    for (int i = 0; i < 16; i++)
        if (ei_words[1 + 74 * i] != 0u) { is64 = 0; break; }
    g_is64 = is64;
}

// ---------------- zero pass --------------------------------------------------
__global__ void zero_setup() {
    int i = blockIdx.x * blockDim.x + threadIdx.x;
    if (i < NN) g_cnt[i] = 0;
    if (i < NG) g_gcnt[i] = 0;
    if (i < NG * C) g_pool[i] = 0.0f;
}

// ---------------- fused convert + degree + batch count ----------------------
__global__ void convert_fused(const void* __restrict__ ei, const void* __restrict__ batch) {
    int i = blockIdx.x * blockDim.x + threadIdx.x;
    const bool is64 = (g_is64 != 0);
    if (i < NE) {
        int s, d;
        if (is64) {
            const long long* p = (const long long*)ei;
            s = (int)p[i];
            d = (int)p[NE + i];
        } else {
            const int* p = (const int*)ei;
            s = p[i];
            d = p[NE + i];
        }
        g_src[i] = s;
        g_dst[i] = d;
        atomicAdd(&g_cnt[d], 1);
    }
    if (i < NN) {
        int b;
        if (is64) b = (int)((const long long*)batch)[i];
        else      b = ((const int*)batch)[i];
        g_batch[i] = b;
        atomicAdd(&g_gcnt[b], 1);
    }
}

// ---------------- 3-stage parallel scan --------------------------------------
__global__ void scan1() {   // 196 blocks x 256: block degree sums
    __shared__ int red[256];
    const int tid = threadIdx.x;
    int i = blockIdx.x * 256 + tid;
    red[tid] = (i < NN) ? g_cnt[i] : 0;
    __syncthreads();
    for (int s = 128; s > 0; s >>= 1) {
        if (tid < s) red[tid] += red[tid + s];
        __syncthreads();
    }
    if (tid == 0) g_part[blockIdx.x] = red[0];
}

__global__ void scan2() {   // 1 block x 256: scan partials + ginv + off[NN]
    __shared__ int sc[256];
    const int t = threadIdx.x;
    int v = (t < 196) ? g_part[t] : 0;
    sc[t] = v;
    __syncthreads();
    for (int d = 1; d < 256; d <<= 1) {
        int val = sc[t];
        int add = (t >= d) ? sc[t - d] : 0;
        __syncthreads();
        sc[t] = val + add;
        __syncthreads();
    }
    if (t < 196) g_pbase[t] = sc[t] - v;
    if (t == 0) g_off[NN] = NE;
    if (t < NG) g_ginv[t] = 1.0f / fmaxf((float)g_gcnt[t], 1.0f);
}

__global__ void scan3() {   // 196 blocks x 256: offsets + cursors + inv
    __shared__ int sc[256];
    const int tid = threadIdx.x;
    int i = blockIdx.x * 256 + tid;
    int v = (i < NN) ? g_cnt[i] : 0;
    sc[tid] = v;
    __syncthreads();
    for (int d = 1; d < 256; d <<= 1) {
        int val = sc[tid];
        int add = (tid >= d) ? sc[tid - d] : 0;
        __syncthreads();
        sc[tid] = val + add;
        __syncthreads();
    }
    if (i < NN) {
        int excl = sc[tid] - v + g_pbase[blockIdx.x];
        g_off[i] = excl;
        g_cur[i] = excl;
        g_inv[i] = 1.0f / fmaxf((float)v, 1.0f);
    }
}

__global__ void fill_kernel() {
    int e = blockIdx.x * blockDim.x + threadIdx.x;
    if (e < NE) {
        int dst = g_dst[e];
        int pos = atomicAdd(&g_cur[dst], 1);
        g_adj[pos] = g_src[e];
    }
}

// ---------------- weight prep: split all layers ------------------------------
__global__ void prep_all(const float* __restrict__ Wl0, const float* __restrict__ Wr0,
                         const float* __restrict__ Wl1, const float* __restrict__ Wr1,
                         const float* __restrict__ Wl2, const float* __restrict__ Wr2) {
    int idx = blockIdx.x * blockDim.x + threadIdx.x;   // 3*16384
    if (idx >= 3 * 16384) return;
    int layer = idx >> 14;
    int rem = idx & 16383;
    int s = rem >> 13;
    int n = (rem >> 6) & 127;
    int w = rem & 63;
    const float* W;
    if (layer == 0)      W = s ? Wr0 : Wl0;
    else if (layer == 1) W = s ? Wr1 : Wl1;
    else                 W = s ? Wr2 : Wl2;
    float a = W[n * 128 + 2 * w];
    float b = W[n * 128 + 2 * w + 1];
    uint32_t hi, lo;
    split2(a, b, hi, lo);
    uint32_t* Bp = (uint32_t*)g_Bp4[layer];
    Bp[(s * 128 + n) * 128 + w] = hi;
    Bp[(s * 128 + n) * 128 + 64 + w] = lo;
}

// ---------------- split x into g_hsA ----------------------------------------
__global__ void split_x(const float* __restrict__ x) {
    int id = blockIdx.x * blockDim.x + threadIdx.x;  // NN*32
    if (id >= NN * 32) return;
    int node = id >> 5;
    int f4 = id & 31;
    const float4 v = *(const float4*)(x + (size_t)node * C + f4 * 4);
    uint32_t h0, l0, h1, l1;
    split2(v.x, v.y, h0, l0);
    split2(v.z, v.w, h1, l1);
    uint32_t* out = (uint32_t*)g_hsA4;
    *(uint2*)(out + (size_t)node * 128 + f4 * 2) = make_uint2(h0, h1);
    *(uint2*)(out + (size_t)node * 128 + 64 + f4 * 2) = make_uint2(l0, l1);
}

// ---------------- mean aggregation (unroll x4, MLP=4) + fused split ---------
__global__ void gather_kernel(int in_sel, const float* __restrict__ x) {
    const float* hin = (in_sel == 0) ? x : ((in_sel == 1) ? g_h0 : g_h1);
    int gid = blockIdx.x * blockDim.x + threadIdx.x;
    int node = gid >> 5;
    int lane = gid & 31;
    if (node >= NN) return;
    const int beg = g_off[node];
    const int end = g_off[node + 1];
    const int co = lane * 4;
    float4 a0 = make_float4(0.f, 0.f, 0.f, 0.f);
    float4 a1 = make_float4(0.f, 0.f, 0.f, 0.f);
    float4 a2 = make_float4(0.f, 0.f, 0.f, 0.f);
    float4 a3 = make_float4(0.f, 0.f, 0.f, 0.f);
    int i = beg;
    const int n4 = beg + ((end - beg) & ~3);
    for (; i < n4; i += 4) {
        int s0 = g_adj[i], s1 = g_adj[i + 1], s2 = g_adj[i + 2], s3 = g_adj[i + 3];
        float4 v0 = *(const float4*)(hin + (size_t)s0 * C + co);
        float4 v1 = *(const float4*)(hin + (size_t)s1 * C + co);
        float4 v2 = *(const float4*)(hin + (size_t)s2 * C + co);
        float4 v3 = *(const float4*)(hin + (size_t)s3 * C + co);
        a0.x += v0.x; a0.y += v0.y; a0.z += v0.z; a0.w += v0.w;
        a1.x += v1.x; a1.y += v1.y; a1.z += v1.z; a1.w += v1.w;
        a2.x += v2.x; a2.y += v2.y; a2.z += v2.z; a2.w += v2.w;
        a3.x += v3.x; a3.y += v3.y; a3.z += v3.z; a3.w += v3.w;
    }
    for (; i < end; i++) {
        int s0 = g_adj[i];
        float4 v0 = *(const float4*)(hin + (size_t)s0 * C + co);
        a0.x += v0.x; a0.y += v0.y; a0.z += v0.z; a0.w += v0.w;
    }
    a0.x += a1.x + a2.x + a3.x;
    a0.y += a1.y + a2.y + a3.y;
    a0.z += a1.z + a2.z + a3.z;
    a0.w += a1.w + a2.w + a3.w;
    const float s = g_inv[node];
    a0.x *= s; a0.y *= s; a0.z *= s; a0.w *= s;
    uint32_t h0, l0, h1, l1;
    split2(a0.x, a0.y, h0, l0);
    split2(a0.z, a0.w, h1, l1);
    uint32_t* out = (uint32_t*)g_aggs4;
    *(uint2*)(out + (size_t)node * 128 + lane * 2) = make_uint2(h0, h1);
    *(uint2*)(out + (size_t)node * 128 + 64 + lane * 2) = make_uint2(l0, l1);
}

// ---------------- tensor-core SAGE layer (mma.sync bf16) --------------------
// 8 warps in 4x2 grid: each warp 32 rows x 64 cols. 3-pairing hi/lo split.
#define RSW 132
#define A_WORDS (128 * RSW)
#define SMEM_WORDS (3 * A_WORDS)   // A, B0, B1 = 202.75KB

__global__ void __launch_bounds__(256, 1) sage_gemm_mma(
    int layer, int hs_in_sel, int out_sel, int do_split,
    const float* __restrict__ bl)
{
    extern __shared__ uint32_t smem[];
    uint32_t* As  = smem;
    uint32_t* B0s = smem + A_WORDS;
    uint32_t* B1s = smem + 2 * A_WORDS;

    const uint32_t* Ain0 = (const uint32_t*)g_aggs4;
    const uint32_t* Ain1 = hs_in_sel ? (const uint32_t*)g_hsB4 : (const uint32_t*)g_hsA4;
    uint32_t* hs_out = hs_in_sel ? (uint32_t*)g_hsA4 : (uint32_t*)g_hsB4;
    float* hout = out_sel ? g_h1 : g_h0;

    const int tid = threadIdx.x;
    const int wid = tid >> 5;
    const int lane = tid & 31;
    const int gid = lane >> 2;
    const int tig = lane & 3;
    const int wr = wid & 3;     // row group (32 rows)
    const int wc = wid >> 2;    // col half (64 cols)

    // Load all B (2 sources x 128 n x 128 words) into SMEM, padded rows.
    {
        const uint4* Bp = g_Bp4[layer];
#pragma unroll
        for (int i = 0; i < 32; i++) {
            int id = tid + 256 * i;          // 8192 uint4
            int s = id >> 12;
            int n = (id >> 5) & 127;
            int q = id & 31;
            uint4 v = Bp[id];
            uint32_t* dst = (s ? B1s : B0s) + n * RSW + q * 4;
            *(uint4*)dst = v;
        }
    }

    for (int tile = blockIdx.x; tile < NT; tile += gridDim.x) {
        const int mbase = tile * 128;
        float acc[2][8][4];
#pragma unroll
        for (int m = 0; m < 2; m++)
#pragma unroll
            for (int nf = 0; nf < 8; nf++)
#pragma unroll
                for (int i = 0; i < 4; i++) acc[m][nf][i] = 0.0f;

        for (int s = 0; s < 2; s++) {
            const uint32_t* Ag = s ? Ain1 : Ain0;
            const uint32_t* Bs = s ? B1s : B0s;
            __syncthreads();
            // fill A tile: 128 rows x 128 words
#pragma unroll
            for (int i = 0; i < 16; i++) {
                int id = tid + 256 * i;
                int r = id >> 5;
                int q = id & 31;
                int grow = mbase + r;
                if (grow >= NN) grow = 0;
                uint4 v = *(const uint4*)(Ag + (size_t)grow * 128 + q * 4);
                *(uint4*)(As + r * RSW + q * 4) = v;
            }
            __syncthreads();

            const uint32_t* Aw = As + (wr * 32 + gid) * RSW + tig;
            const uint32_t* Bw = Bs + (wc * 64 + gid) * RSW + tig;
            for (int ks = 0; ks < 8; ks++) {
                const uint32_t* Ap = Aw + ks * 8;
                uint32_t ah[2][4], al[2][4];
#pragma unroll
                for (int m = 0; m < 2; m++) {
                    const uint32_t* Am = Ap + m * (16 * RSW);
                    ah[m][0] = Am[0];            ah[m][2] = Am[4];
                    ah[m][1] = Am[8 * RSW];      ah[m][3] = Am[8 * RSW + 4];
                    al[m][0] = Am[64];           al[m][2] = Am[68];
                    al[m][1] = Am[8 * RSW + 64]; al[m][3] = Am[8 * RSW + 68];
                }
                const uint32_t* Bq = Bw + ks * 8;
#pragma unroll
                for (int nf = 0; nf < 8; nf++) {
                    const uint32_t* Bn = Bq + nf * (8 * RSW);
                    uint32_t bh0 = Bn[0], bh1 = Bn[4];
                    uint32_t bl0 = Bn[64], bl1 = Bn[68];
#pragma unroll
                    for (int m = 0; m < 2; m++) {
                        mma_bf16(acc[m][nf], ah[m][0], ah[m][1], ah[m][2], ah[m][3], bh0, bh1);
                        mma_bf16(acc[m][nf], al[m][0], al[m][1], al[m][2], al[m][3], bh0, bh1);
                        mma_bf16(acc[m][nf], ah[m][0], ah[m][1], ah[m][2], ah[m][3], bl0, bl1);
                    }
                }
            }
        }

        // epilogue: bias + relu + fp32 store + optional split store
#pragma unroll
        for (int m = 0; m < 2; m++) {
            const int r0 = mbase + wr * 32 + m * 16 + gid;
            const int r1 = r0 + 8;
#pragma unroll
            for (int nf = 0; nf < 8; nf++) {
                const int col = wc * 64 + nf * 8 + tig * 2;
                const float2 bb = *(const float2*)(bl + col);
                float v00 = fmaxf(acc[m][nf][0] + bb.x, 0.0f);
                float v01 = fmaxf(acc[m][nf][1] + bb.y, 0.0f);
                float v10 = fmaxf(acc[m][nf][2] + bb.x, 0.0f);
                float v11 = fmaxf(acc[m][nf][3] + bb.y, 0.0f);
                if (r0 < NN) *(float2*)(hout + (size_t)r0 * C + col) = make_float2(v00, v01);
                if (r1 < NN) *(float2*)(hout + (size_t)r1 * C + col) = make_float2(v10, v11);
                if (do_split) {
                    const int w = col >> 1;   // word index = col/2
                    uint32_t hi, lo;
                    if (r0 < NN) {
                        split2(v00, v01, hi, lo);
                        hs_out[(size_t)r0 * 128 + w] = hi;
                        hs_out[(size_t)r0 * 128 + 64 + w] = lo;
                    }
                    if (r1 < NN) {
                        split2(v10, v11, hi, lo);
                        hs_out[(size_t)r1 * 128 + w] = hi;
                        hs_out[(size_t)r1 * 128 + 64 + w] = lo;
                    }
                }
            }
        }
    }
}

// ---------------- global mean pool: run-length over sorted batch ------------
__global__ void pool_kernel() {
    int gid = blockIdx.x * blockDim.x + threadIdx.x;
    int warp = gid >> 5;
    int lane = gid & 31;
    int n0 = warp * 16;
    if (n0 >= NN) return;
    int cur = g_batch[n0];
    float4 acc = make_float4(0.f, 0.f, 0.f, 0.f);
    const int co = lane * 4;
#pragma unroll
    for (int k = 0; k < 16; k++) {
        int node = n0 + k;
        if (node >= NN) break;
        int b = g_batch[node];
        if (b != cur) {
            float* p = g_pool + cur * C + co;
            atomicAdd(p + 0, acc.x);
            atomicAdd(p + 1, acc.y);
            atomicAdd(p + 2, acc.z);
            atomicAdd(p + 3, acc.w);
            acc = make_float4(0.f, 0.f, 0.f, 0.f);
            cur = b;
        }
        const float4 v = *(const float4*)(g_h0 + (size_t)node * C + co);
        acc.x += v.x; acc.y += v.y; acc.z += v.z; acc.w += v.w;
    }
    float* p = g_pool + cur * C + co;
    atomicAdd(p + 0, acc.x);
    atomicAdd(p + 1, acc.y);
    atomicAdd(p + 2, acc.z);
    atomicAdd(p + 3, acc.w);
}

// ---------------- head ------------------------------------------------------
__global__ void out_kernel(const float* __restrict__ W_lin,
                           const float* __restrict__ b_lin,
                           float* __restrict__ out) {
    int g = blockIdx.x;
    int c = threadIdx.x;
    __shared__ float sv[C];
    sv[c] = g_pool[g * C + c] * g_ginv[g];
    __syncthreads();
    if (c < OUTC) {
        float s = b_lin[c];
#pragma unroll
        for (int k = 0; k < C; k++) s += sv[k] * W_lin[c * C + k];
        out[g * OUTC + c] = s;
    }
}

// ---------------- launch ----------------------------------------------------
extern "C" void kernel_launch(void* const* d_in, const int* in_sizes, int n_in,
                              void* d_out, int out_size) {
    const float* x      = (const float*)d_in[0];
    const void*  ei     = d_in[1];
    const void*  batch  = d_in[2];
    const float* Wl[3]  = {(const float*)d_in[3], (const float*)d_in[6], (const float*)d_in[9]};
    const float* blv[3] = {(const float*)d_in[4], (const float*)d_in[7], (const float*)d_in[10]};
    const float* Wr[3]  = {(const float*)d_in[5], (const float*)d_in[8], (const float*)d_in[11]};
    const float* W_lin  = (const float*)d_in[12];
    const float* b_lin  = (const float*)d_in[13];
    float* out = (float*)d_out;

    static int smem_set = 0;
    if (!smem_set) {
        cudaFuncSetAttribute(sage_gemm_mma,
                             cudaFuncAttributeMaxDynamicSharedMemorySize,
                             SMEM_WORDS * 4);
        smem_set = 1;
    }

    const int TB = 256;
    const int gE = (NE + TB - 1) / TB;       // 2344
    const int gN = (NN + TB - 1) / TB;       // 196
    const int gW = (NN * 32 + TB - 1) / TB;  // 6250
    const int gP = ((NN + 15) / 16 * 32 + TB - 1) / TB;  // 391

    detect_kernel<<<1, 1>>>((const unsigned int*)ei);
    zero_setup<<<gN, TB>>>();
    convert_fused<<<gE, TB>>>(ei, batch);
    scan1<<<gN, TB>>>();
    scan2<<<1, 256>>>();
    scan3<<<gN, TB>>>();
    fill_kernel<<<gE, TB>>>();

    prep_all<<<(3 * 16384 + TB - 1) / TB, TB>>>(Wl[0], Wr[0], Wl[1], Wr[1], Wl[2], Wr[2]);
    split_x<<<gW, TB>>>(x);

    // l0: gather(x),  hs_in=A(x),  fp32 out h0, split out -> B
    // l1: gather(h0), hs_in=B,     fp32 out h1, split out -> A
    // l2: gather(h1), hs_in=A,     fp32 out h0, no split
    const int in_sel[3]  = {0, 1, 2};
    const int hs_sel[3]  = {0, 1, 0};
    const int out_sel[3] = {0, 1, 0};
    const int do_spl[3]  = {1, 1, 0};
    for (int l = 0; l < 3; l++) {
        gather_kernel<<<gW, TB>>>(in_sel[l], x);
        sage_gemm_mma<<<148, TB, SMEM_WORDS * 4>>>(l, hs_sel[l], out_sel[l], do_spl[l], blv[l]);
    }

    pool_kernel<<<gP, TB>>>();
    out_kernel<<<NG, C>>>(W_lin, b_lin, out);
}